// round 2
// baseline (speedup 1.0000x reference)
#include <cuda_runtime.h>
#include <math.h>

// AMPS fast log-prob.
//   chain(n, bs): v = e0^T * Prod_{m=0..n} A(n,m,bs);  A = plane-selected 4x4 of tri_up[n(n+1)/2+m]
//   logits[n+1][bs][p] = v . diag[n+1][:,p];  logits[0][bs][p] = diag[0,0,p]
//   out[bs] = sum_n ( logsoftmax(logits[n])[sel] )
//
// Split: vector prefix m in [0,256) per warp; 64-step 4x4 matrix chunks for m>=256;
// combine + finalize kernels. All scratch in static __device__ arrays.

#define NN      1024
#define NCHAIN  1023
#define SL      256
#define SMCH    64
#define MAXC    12
#define FULLM   0xffffffffu

// scratch
__device__ float g_vL[NCHAIN * 32];                // [n][bs][r]
__device__ float g_M[(NCHAIN - SL) * MAXC * 128];  // [(n-256)][c][bs*16 + l*4 + r]
__device__ float g_logits[NN * 16];                // [nn][bs][p]  (p<2 used)
__device__ unsigned int g_sel[NN];                 // bit bs = plane index (0 if data==1 else 1)

// ---------------- prep: selector bits + logits[0] ----------------
__global__ void amps_prep(const float* __restrict__ data, const float* __restrict__ diag) {
    int m = blockIdx.x * blockDim.x + threadIdx.x;
    if (m < NN) {
        unsigned int s = 0;
#pragma unroll
        for (int b = 0; b < 8; b++)
            s |= ((data[b * NN + m] != 0.0f) ? 0u : 1u) << b;
        g_sel[m] = s;
    }
    if (m < 16) {
        // logits[0][bs][p] = diag[0,0,p]
        g_logits[m] = diag[m & 1];
    }
}

// ---------------- main: vector prefixes + matrix chunks ----------------
// blocks [0,128): vector warps, n = blk*8 + warp
// blocks [128, 128+1151): chunk warps, flat = (blk-128)*8 + warp -> (n, c)
__global__ __launch_bounds__(256) void amps_main(const float* __restrict__ tri) {
    const int warp = threadIdx.x >> 5;
    const int lane = threadIdx.x & 31;
    const int bs = lane >> 2;

    if (blockIdx.x < 128) {
        // ------- vector prefix for chain n -------
        const int n = blockIdx.x * 8 + warp;
        if (n >= NCHAIN) return;
        const int r = lane & 3;
        const long t0 = (long)n * (n + 1) / 2;
        const float* p = tri + t0 * 32;
        const int mEnd = (n < SL - 1) ? n : (SL - 1);

        // init from m = 0 : v[j] = line[j*2 + ps]
        float w = __ldg(p + lane);
        unsigned int ps = (g_sel[0] >> bs) & 1u;
        float v0 = __shfl_sync(FULLM, w, (int)(ps + 0));
        float v1 = __shfl_sync(FULLM, w, (int)(ps + 2));
        float v2 = __shfl_sync(FULLM, w, (int)(ps + 4));
        float v3 = __shfl_sync(FULLM, w, (int)(ps + 6));
        p += 32;

        float wn = (mEnd >= 1) ? __ldg(p + lane) : 0.0f;
        for (int m = 1; m <= mEnd; m++) {
            w = wn;
            if (m < mEnd) wn = __ldg(p + 32 + lane);
            unsigned int psm = (g_sel[m] >> bs) & 1u;
            // A[l][r] = line[l*8 + r*2 + ps]
            int o = r * 2 + (int)psm;
            float a0 = __shfl_sync(FULLM, w, o);
            float a1 = __shfl_sync(FULLM, w, o + 8);
            float a2 = __shfl_sync(FULLM, w, o + 16);
            float a3 = __shfl_sync(FULLM, w, o + 24);
            float nv = fmaf(a0, v0, fmaf(a1, v1, fmaf(a2, v2, a3 * v3)));
            // regather full v across the quad
            int qb = lane & ~3;
            v0 = __shfl_sync(FULLM, nv, qb + 0);
            v1 = __shfl_sync(FULLM, nv, qb + 1);
            v2 = __shfl_sync(FULLM, nv, qb + 2);
            v3 = __shfl_sync(FULLM, nv, qb + 3);
            p += 32;
        }
        float vr = (r == 0) ? v0 : ((r == 1) ? v1 : ((r == 2) ? v2 : v3));
        g_vL[n * 32 + lane] = vr;
    } else {
        // ------- matrix chunk (n, c) : product of A over m in [256+64c, min(n, 255+64(c+1))] -------
        const int flat = (blockIdx.x - 128) * 8 + warp;
        const int n = SL + flat / MAXC;
        const int c = flat % MAXC;
        if (n >= NCHAIN) return;
        const int k = n - SL;
        if (c > (k >> 6)) return;
        const int l = lane & 3;
        const int mS = SL + c * SMCH;
        const int mE = min(n, mS + SMCH - 1);
        const long t0 = (long)n * (n + 1) / 2;
        const float* p = tri + (t0 + mS) * 32;

        // init M = A(n, mS): row l -> m0..m3 = line[l*8 + j*2 + ps]
        float w = __ldg(p + lane);
        unsigned int ps = (g_sel[mS] >> bs) & 1u;
        int lo = l * 8 + (int)ps;
        float m0 = __shfl_sync(FULLM, w, lo + 0);
        float m1 = __shfl_sync(FULLM, w, lo + 2);
        float m2 = __shfl_sync(FULLM, w, lo + 4);
        float m3 = __shfl_sync(FULLM, w, lo + 6);
        p += 32;

        float wn = (mS < mE) ? __ldg(p + lane) : 0.0f;
        for (int m = mS + 1; m <= mE; m++) {
            w = wn;
            if (m < mE) wn = __ldg(p + 32 + lane);
            unsigned int psm = (g_sel[m] >> bs) & 1u;
            int b0 = (int)psm;
            // a[kk][j] = line[kk*8 + j*2 + ps]
            float a00 = __shfl_sync(FULLM, w, b0 + 0);
            float a01 = __shfl_sync(FULLM, w, b0 + 2);
            float a02 = __shfl_sync(FULLM, w, b0 + 4);
            float a03 = __shfl_sync(FULLM, w, b0 + 6);
            float a10 = __shfl_sync(FULLM, w, b0 + 8);
            float a11 = __shfl_sync(FULLM, w, b0 + 10);
            float a12 = __shfl_sync(FULLM, w, b0 + 12);
            float a13 = __shfl_sync(FULLM, w, b0 + 14);
            float a20 = __shfl_sync(FULLM, w, b0 + 16);
            float a21 = __shfl_sync(FULLM, w, b0 + 18);
            float a22 = __shfl_sync(FULLM, w, b0 + 20);
            float a23 = __shfl_sync(FULLM, w, b0 + 22);
            float a30 = __shfl_sync(FULLM, w, b0 + 24);
            float a31 = __shfl_sync(FULLM, w, b0 + 26);
            float a32 = __shfl_sync(FULLM, w, b0 + 28);
            float a33 = __shfl_sync(FULLM, w, b0 + 30);
            // row_new = row @ A
            float n0 = fmaf(m0, a00, fmaf(m1, a10, fmaf(m2, a20, m3 * a30)));
            float n1 = fmaf(m0, a01, fmaf(m1, a11, fmaf(m2, a21, m3 * a31)));
            float n2 = fmaf(m0, a02, fmaf(m1, a12, fmaf(m2, a22, m3 * a32)));
            float n3 = fmaf(m0, a03, fmaf(m1, a13, fmaf(m2, a23, m3 * a33)));
            m0 = n0; m1 = n1; m2 = n2; m3 = n3;
            p += 32;
        }
        float4* dst = (float4*)&g_M[((long)k * MAXC + c) * 128 + bs * 16 + l * 4];
        *dst = make_float4(m0, m1, m2, m3);
    }
}

// ---------------- combine: v = vL @ M_c... ; logits ----------------
__global__ __launch_bounds__(256) void amps_combine(const float* __restrict__ diag) {
    const int warp = threadIdx.x >> 5;
    const int lane = threadIdx.x & 31;
    const int bs = lane >> 2;
    const int r = lane & 3;
    const int n = blockIdx.x * 8 + warp;
    if (n >= NCHAIN) return;

    float4 vv = *(const float4*)&g_vL[n * 32 + bs * 4];
    float v0 = vv.x, v1 = vv.y, v2 = vv.z, v3 = vv.w;

    if (n >= SL) {
        const int k = n - SL;
        const int nch = (k >> 6) + 1;
        for (int c = 0; c < nch; c++) {
            const float* Mb = &g_M[((long)k * MAXC + c) * 128 + bs * 16];
            float a0 = Mb[0 + r];
            float a1 = Mb[4 + r];
            float a2 = Mb[8 + r];
            float a3 = Mb[12 + r];
            float nv = fmaf(a0, v0, fmaf(a1, v1, fmaf(a2, v2, a3 * v3)));
            int qb = lane & ~3;
            v0 = __shfl_sync(FULLM, nv, qb + 0);
            v1 = __shfl_sync(FULLM, nv, qb + 1);
            v2 = __shfl_sync(FULLM, nv, qb + 2);
            v3 = __shfl_sync(FULLM, nv, qb + 3);
        }
    }
    if (r < 2) {
        const int pp = r;
        const float* dg = diag + (long)(n + 1) * 8;
        float x = fmaf(v0, dg[0 + pp], fmaf(v1, dg[2 + pp], fmaf(v2, dg[4 + pp], v3 * dg[6 + pp])));
        g_logits[(n + 1) * 16 + bs * 2 + pp] = x;
    }
}

// ---------------- finalize: log-softmax + masked sum ----------------
__global__ void amps_finalize(float* __restrict__ out) {
    const int warp = threadIdx.x >> 5;  // = bs
    const int lane = threadIdx.x & 31;
    const int bs = warp;
    float acc = 0.0f;
    for (int nn = lane; nn < NN; nn += 32) {
        float x0 = g_logits[nn * 16 + bs * 2 + 0];
        float x1 = g_logits[nn * 16 + bs * 2 + 1];
        float mx = fmaxf(x0, x1);
        float lse = mx + log1pf(expf(-fabsf(x0 - x1)));
        unsigned int ps = (g_sel[nn] >> bs) & 1u;
        acc += (ps ? x1 : x0) - lse;
    }
#pragma unroll
    for (int o = 16; o; o >>= 1) acc += __shfl_xor_sync(FULLM, acc, o);
    if (lane == 0) out[bs] = acc;
}

extern "C" void kernel_launch(void* const* d_in, const int* in_sizes, int n_in,
                              void* d_out, int out_size) {
    const float* data = (const float*)d_in[0];
    const float* tri  = (const float*)d_in[1];
    const float* diag = (const float*)d_in[2];
    float* out = (float*)d_out;

    amps_prep<<<4, 256>>>(data, diag);
    // vector blocks: 128;  chunk blocks: ceil(767*12 / 8) = 1151
    amps_main<<<128 + 1151, 256>>>(tri);
    amps_combine<<<128, 256>>>(diag);
    amps_finalize<<<1, 256>>>(out);
}

// round 5
// speedup vs baseline: 1.0684x; 1.0684x over previous
#include <cuda_runtime.h>
#include <math.h>

// AMPS fast log-prob, v3: shuffle-free full-state-lane main kernel.
//   chain(n, bs): v = e0^T * Prod_{m=0..n} A(n,m,bs);  A = plane-selected 4x4 of tri_up[n(n+1)/2+m]
//   logits[n+1][bs][p] = v . diag[n+1][:,p];  out[bs] = sum_n logsoftmax(logits[n])[sel]
// Main kernel: vector warps (lane = (chain, sample), full v[4] in regs) for m<256;
//              chunk warps  (lane = (chunk, sample),  full P[16] in regs) for 64-step chunks m>=256.
// A distributed via warp-private smem tiles (coop LDG.128 -> STS.128 -> LDS.128), no shfl.

#define NN    1024
#define NCH   1023
#define SL    256
#define SMCH  64
#define MAXC  12
#define FULLM 0xffffffffu
#define TT    8
#define VBLK  32      // 32 blocks * 8 warps * 4 chains = 1024 >= 1023 chains
#define NCID  4980    // total (k,c) chunks
#define CBLK  156     // ceil(4980/4/8)

__device__ float g_vL[NCH * 32];           // [n][bs*4+j]
__device__ float g_M[767 * MAXC * 128];    // [k][c][bs*16 + i*4 + j]
__device__ float g_contrib[8 * 1024];      // [bs][out position]

__constant__ int c_off[13] = {0,767,1470,2109,2684,3195,3642,4025,4344,4599,4790,4917,4980};

__global__ __launch_bounds__(256, 1) void amps_main(const float* __restrict__ data,
                                                    const float* __restrict__ tri) {
    __shared__ unsigned ssel[NN];
    __shared__ float4 sm[8 * 264];   // per warp: 4 groups * 66 float4 (8 steps * 8 slots + 2 skew)

    const int tid = threadIdx.x, warp = tid >> 5, lane = tid & 31;
    const int g = lane >> 3, bs = lane & 7;

    // block-local selector bits: bit bs of ssel[m] = plane (0 if data!=0 else 1)
    for (int m = tid; m < NN; m += 256) {
        unsigned s = 0;
#pragma unroll
        for (int b = 0; b < 8; b++) s |= ((data[b * NN + m] != 0.0f) ? 0u : 1u) << b;
        ssel[m] = s;
    }
    __syncthreads();

    float4* smw = sm + warp * 264 + g * 66;
    const float4* tri4 = (const float4*)tri;

    if (blockIdx.x < VBLK) {
        // ---------------- vector prefix: chain n, sample bs, full v in regs ----------------
        const int n = (blockIdx.x * 8 + warp) * 4 + g;
        const bool valid = (n < NCH);
        const int nc = valid ? n : (NCH - 1);
        const size_t t0 = (size_t)nc * (nc + 1) / 2;
        const int mEnd = valid ? min(nc, SL - 1) : -1;
        const int steps = mEnd + 1;
        const int ws = __reduce_max_sync(FULLM, steps);
        const float4* base = tri4 + t0 * 8;
        const int mE0 = (mEnd > 0) ? mEnd : 0;

        float v0 = 1.0f, v1 = 0.0f, v2 = 0.0f, v3 = 0.0f;
        float4 r[TT];
#pragma unroll
        for (int t = 0; t < TT; t++) r[t] = __ldg(base + (size_t)min(t, mE0) * 8 + bs);

        for (int mt = 0; mt < ws; mt += TT) {
            __syncwarp();
#pragma unroll
            for (int t = 0; t < TT; t++) smw[t * 8 + bs] = r[t];
            __syncwarp();
            if (mt + TT < ws) {
#pragma unroll
                for (int t = 0; t < TT; t++)
                    r[t] = __ldg(base + (size_t)min(mt + TT + t, mE0) * 8 + bs);
            }
#pragma unroll
            for (int t = 0; t < TT; t++) {
                const int m = mt + t;
                const unsigned sw = ssel[m];
                const bool p = (sw >> bs) & 1u;
                float a[16];
#pragma unroll
                for (int q = 0; q < 8; q++) {
                    float4 w = smw[t * 8 + q];
                    a[(q >> 1) * 4 + (q & 1) * 2]     = p ? w.y : w.x;
                    a[(q >> 1) * 4 + (q & 1) * 2 + 1] = p ? w.w : w.z;
                }
                if (m <= mEnd) {
                    float n0 = v0 * a[0] + v1 * a[4] + v2 * a[8]  + v3 * a[12];
                    float n1 = v0 * a[1] + v1 * a[5] + v2 * a[9]  + v3 * a[13];
                    float n2 = v0 * a[2] + v1 * a[6] + v2 * a[10] + v3 * a[14];
                    float n3 = v0 * a[3] + v1 * a[7] + v2 * a[11] + v3 * a[15];
                    v0 = n0; v1 = n1; v2 = n2; v3 = n3;
                }
            }
        }
        if (valid) {
            *(float4*)&g_vL[n * 32 + bs * 4] = make_float4(v0, v1, v2, v3);
        }
    } else {
        // ---------------- matrix chunk: (k=n-256, c), sample bs, full P in regs ----------------
        const int cid = ((blockIdx.x - VBLK) * 8 + warp) * 4 + g;
        const bool valid = (cid < NCID);
        const int cc = valid ? cid : 0;
        int c = 0;
#pragma unroll
        for (int j = 1; j < 12; j++) if (cc >= c_off[j]) c = j;
        const int k = 64 * c + (cc - c_off[c]);
        const int n = SL + k;
        const size_t t0 = (size_t)n * (n + 1) / 2;
        const int mS = SL + 64 * c;
        const int mE = min(n, mS + SMCH - 1);
        const int steps = valid ? (mE - mS + 1) : 0;
        const int ws = __reduce_max_sync(FULLM, steps);
        const float4* base = tri4 + (t0 + mS) * 8;
        const int sc = (steps > 1) ? (steps - 1) : 0;

        float P[16];
#pragma unroll
        for (int q = 0; q < 16; q++) P[q] = (q % 5 == 0) ? 1.0f : 0.0f;

        float4 r[TT];
#pragma unroll
        for (int t = 0; t < TT; t++) r[t] = __ldg(base + (size_t)min(t, sc) * 8 + bs);

        for (int st = 0; st < ws; st += TT) {
            __syncwarp();
#pragma unroll
            for (int t = 0; t < TT; t++) smw[t * 8 + bs] = r[t];
            __syncwarp();
            if (st + TT < ws) {
#pragma unroll
                for (int t = 0; t < TT; t++)
                    r[t] = __ldg(base + (size_t)min(st + TT + t, sc) * 8 + bs);
            }
#pragma unroll
            for (int t = 0; t < TT; t++) {
                const int s = st + t;
                const unsigned sw = ssel[mS + s];          // mS+s <= 1023
                const bool p = (sw >> bs) & 1u;
                float a[16];
#pragma unroll
                for (int q = 0; q < 8; q++) {
                    float4 w = smw[t * 8 + q];
                    a[(q >> 1) * 4 + (q & 1) * 2]     = p ? w.y : w.x;
                    a[(q >> 1) * 4 + (q & 1) * 2 + 1] = p ? w.w : w.z;
                }
                if (s < steps) {
#pragma unroll
                    for (int i = 0; i < 4; i++) {
                        float q0 = P[i*4+0]*a[0] + P[i*4+1]*a[4] + P[i*4+2]*a[8]  + P[i*4+3]*a[12];
                        float q1 = P[i*4+0]*a[1] + P[i*4+1]*a[5] + P[i*4+2]*a[9]  + P[i*4+3]*a[13];
                        float q2 = P[i*4+0]*a[2] + P[i*4+1]*a[6] + P[i*4+2]*a[10] + P[i*4+3]*a[14];
                        float q3 = P[i*4+0]*a[3] + P[i*4+1]*a[7] + P[i*4+2]*a[11] + P[i*4+3]*a[15];
                        P[i*4+0] = q0; P[i*4+1] = q1; P[i*4+2] = q2; P[i*4+3] = q3;
                    }
                }
            }
        }
        if (valid) {
            float4* dst = (float4*)&g_M[((size_t)k * MAXC + c) * 128 + bs * 16];
#pragma unroll
            for (int i = 0; i < 4; i++)
                dst[i] = make_float4(P[i*4], P[i*4+1], P[i*4+2], P[i*4+3]);
        }
    }
}

// ---------------- combine: v = vL @ M_c...; fused log-softmax contribution ----------------
__global__ __launch_bounds__(256) void amps_combine(const float* __restrict__ data,
                                                    const float* __restrict__ diag) {
    const int warp = threadIdx.x >> 5, lane = threadIdx.x & 31;
    const int bs = lane >> 2, rr = lane & 3;
    const int n = blockIdx.x * 8 + warp;
    if (n >= NCH) return;

    float4 vv = *(const float4*)&g_vL[n * 32 + bs * 4];
    float v0 = vv.x, v1 = vv.y, v2 = vv.z, v3 = vv.w;

    if (n >= SL) {
        const int k = n - SL;
        const int nch = (k >> 6) + 1;
        for (int c = 0; c < nch; c++) {
            const float* Mb = &g_M[((size_t)k * MAXC + c) * 128 + bs * 16];
            float nv = v0 * Mb[rr] + v1 * Mb[4 + rr] + v2 * Mb[8 + rr] + v3 * Mb[12 + rr];
            int qb = lane & ~3;
            v0 = __shfl_sync(FULLM, nv, qb);
            v1 = __shfl_sync(FULLM, nv, qb + 1);
            v2 = __shfl_sync(FULLM, nv, qb + 2);
            v3 = __shfl_sync(FULLM, nv, qb + 3);
        }
    }
    const float* dg = diag + (size_t)(n + 1) * 8;
    const int rp = rr & 1;
    float x = v0 * dg[rp] + v1 * dg[2 + rp] + v2 * dg[4 + rp] + v3 * dg[6 + rp];
    float x1 = __shfl_sync(FULLM, x, (lane & ~3) + 1);
    if (rr == 0) {
        float x0 = x;
        float mx = fmaxf(x0, x1);
        float lse = mx + log1pf(expf(-fabsf(x0 - x1)));
        bool p1 = (data[bs * NN + (n + 1)] == 0.0f);   // plane1 if data==0
        g_contrib[bs * 1024 + n + 1] = (p1 ? x1 : x0) - lse;
    }
}

// ---------------- finalize: parallel reduction per sample ----------------
__global__ void amps_finalize(const float* __restrict__ data, const float* __restrict__ diag,
                              float* __restrict__ out) {
    const int bs = blockIdx.x;
    const int tid = threadIdx.x, warp = tid >> 5, lane = tid & 31;
    float4 v = ((const float4*)(g_contrib + bs * 1024))[tid];
    if (tid == 0) {
        float x0 = diag[0], x1 = diag[1];
        float mx = fmaxf(x0, x1);
        float lse = mx + log1pf(expf(-fabsf(x0 - x1)));
        v.x = ((data[bs * NN] == 0.0f) ? x1 : x0) - lse;   // n=0 contribution
    }
    float s = v.x + v.y + v.z + v.w;
#pragma unroll
    for (int o = 16; o; o >>= 1) s += __shfl_xor_sync(FULLM, s, o);
    __shared__ float ws8[8];
    if (lane == 0) ws8[warp] = s;
    __syncthreads();
    if (warp == 0) {
        float t = (lane < 8) ? ws8[lane] : 0.0f;
#pragma unroll
        for (int o = 4; o; o >>= 1) t += __shfl_xor_sync(FULLM, t, o);
        if (lane == 0) out[bs] = t;
    }
}

extern "C" void kernel_launch(void* const* d_in, const int* in_sizes, int n_in,
                              void* d_out, int out_size) {
    const float* data = (const float*)d_in[0];
    const float* tri  = (const float*)d_in[1];
    const float* diag = (const float*)d_in[2];
    float* out = (float*)d_out;

    amps_main<<<VBLK + CBLK, 256>>>(data, tri);
    amps_combine<<<128, 256>>>(data, diag);
    amps_finalize<<<8, 256>>>(data, diag, out);
}

// round 6
// speedup vs baseline: 1.6673x; 1.5606x over previous
#include <cuda_runtime.h>
#include <math.h>

// AMPS fast log-prob, v4: uniform 64-step chunk units, 2 CTAs/SM.
//   chain(n, bs): v = e0^T * Prod_{m=0..n} A(n,m,bs);  A = plane-selected 4x4 of tri_up[n(n+1)/2+m]
//   logits[n+1][bs][p] = v . diag[n+1][:,p];  out[bs] = sum_n logsoftmax(logits[n])[sel]
// Main: every work unit = 64-step 4x4 chunk product (m in [64c, 64c+63]), lane = (chunk, sample),
//       full P[16] in regs, A distributed via warp-private smem tiles (no shfl).
// Combine: v = row0(P_0) @ P_1 @ ... ; fused log-softmax contribution.  Finalize: reduction.

#define NN    1024
#define NCH   1023
#define SMCH  64
#define MAXC  16
#define FULLM 0xffffffffu
#define TT    8
#define NCID  8688
#define NBLK  272     // ceil(8688/4/8)

__device__ float g_M[NCID * 128];         // [cid][bs*16 + i*4 + j]
__device__ float g_contrib[8 * 1024];     // [bs][out position]

__constant__ int c_off[17] = {0,1023,1982,2877,3708,4475,5178,5817,6392,6903,
                              7350,7733,8052,8307,8498,8625,8688};

__global__ __launch_bounds__(256, 2) void amps_main(const float* __restrict__ data,
                                                    const float* __restrict__ tri) {
    __shared__ unsigned ssel[NN];
    __shared__ float4 sm[8 * 264];   // per warp: 4 groups * 66 float4 (8 steps * 8 slots + skew)

    const int tid = threadIdx.x, warp = tid >> 5, lane = tid & 31;
    const int g = lane >> 3, bs = lane & 7;

    // block-local selector bits: bit bs of ssel[m] = plane (0 if data!=0 else 1)
    for (int m = tid; m < NN; m += 256) {
        unsigned s = 0;
#pragma unroll
        for (int b = 0; b < 8; b++) s |= ((data[b * NN + m] != 0.0f) ? 0u : 1u) << b;
        ssel[m] = s;
    }
    __syncthreads();

    float4* smw = sm + warp * 264 + g * 66;
    const float4* tri4 = (const float4*)tri;

    const int cid = (blockIdx.x * 8 + warp) * 4 + g;
    const bool valid = (cid < NCID);
    const int cc = valid ? cid : 0;
    int c = 0;
#pragma unroll
    for (int j = 1; j < 16; j++) if (cc >= c_off[j]) c = j;
    const int n = 64 * c + (cc - c_off[c]);
    const int mS = 64 * c;
    const int mE = min(n, mS + SMCH - 1);
    const int steps = mE - mS + 1;
    const int ws = __reduce_max_sync(FULLM, steps);
    const size_t t0 = (size_t)n * (n + 1) / 2;
    const float4* base = tri4 + (t0 + mS) * 8;
    const int sc = steps - 1;

    float P[16];
#pragma unroll
    for (int q = 0; q < 16; q++) P[q] = (q % 5 == 0) ? 1.0f : 0.0f;

    float4 r[TT];
#pragma unroll
    for (int t = 0; t < TT; t++) r[t] = __ldg(base + (size_t)min(t, sc) * 8 + bs);

    for (int st = 0; st < ws; st += TT) {
        __syncwarp();
#pragma unroll
        for (int t = 0; t < TT; t++) smw[t * 8 + bs] = r[t];
        __syncwarp();
        if (st + TT < ws) {
#pragma unroll
            for (int t = 0; t < TT; t++)
                r[t] = __ldg(base + (size_t)min(st + TT + t, sc) * 8 + bs);
        }
#pragma unroll
        for (int t = 0; t < TT; t++) {
            const int s = st + t;
            const unsigned sw = ssel[mS + s <= (NN - 1) ? mS + s : (NN - 1)];
            const bool p = (sw >> bs) & 1u;
            float a[16];
#pragma unroll
            for (int q = 0; q < 8; q++) {
                float4 w = smw[t * 8 + q];
                a[(q >> 1) * 4 + (q & 1) * 2]     = p ? w.y : w.x;
                a[(q >> 1) * 4 + (q & 1) * 2 + 1] = p ? w.w : w.z;
            }
            if (s < steps) {
#pragma unroll
                for (int i = 0; i < 4; i++) {
                    float q0 = P[i*4+0]*a[0] + P[i*4+1]*a[4] + P[i*4+2]*a[8]  + P[i*4+3]*a[12];
                    float q1 = P[i*4+0]*a[1] + P[i*4+1]*a[5] + P[i*4+2]*a[9]  + P[i*4+3]*a[13];
                    float q2 = P[i*4+0]*a[2] + P[i*4+1]*a[6] + P[i*4+2]*a[10] + P[i*4+3]*a[14];
                    float q3 = P[i*4+0]*a[3] + P[i*4+1]*a[7] + P[i*4+2]*a[11] + P[i*4+3]*a[15];
                    P[i*4+0] = q0; P[i*4+1] = q1; P[i*4+2] = q2; P[i*4+3] = q3;
                }
            }
        }
    }
    if (valid) {
        float4* dst = (float4*)&g_M[(size_t)cid * 128 + bs * 16];
#pragma unroll
        for (int i = 0; i < 4; i++)
            dst[i] = make_float4(P[i*4], P[i*4+1], P[i*4+2], P[i*4+3]);
    }
}

// ---------------- combine: v = row0(P_0) @ P_1 @ ... ; fused log-softmax ----------------
__global__ __launch_bounds__(256) void amps_combine(const float* __restrict__ data,
                                                    const float* __restrict__ diag) {
    const int warp = threadIdx.x >> 5, lane = threadIdx.x & 31;
    const int bs = lane >> 2, rr = lane & 3;
    const int n = blockIdx.x * 8 + warp;
    if (n >= NCH) return;

    // chunk 0: v = e0^T P_0 = row 0 of P_0
    float4 vv = *(const float4*)&g_M[(size_t)n * 128 + bs * 16];  // cid(n,0) = n
    float v0 = vv.x, v1 = vv.y, v2 = vv.z, v3 = vv.w;

    const int nch = (n >> 6) + 1;
    for (int c = 1; c < nch; c++) {
        const int cid = c_off[c] + n - 64 * c;
        const float* Mb = &g_M[(size_t)cid * 128 + bs * 16];
        float nv = v0 * Mb[rr] + v1 * Mb[4 + rr] + v2 * Mb[8 + rr] + v3 * Mb[12 + rr];
        int qb = lane & ~3;
        v0 = __shfl_sync(FULLM, nv, qb);
        v1 = __shfl_sync(FULLM, nv, qb + 1);
        v2 = __shfl_sync(FULLM, nv, qb + 2);
        v3 = __shfl_sync(FULLM, nv, qb + 3);
    }
    const float* dg = diag + (size_t)(n + 1) * 8;
    const int rp = rr & 1;
    float x = v0 * dg[rp] + v1 * dg[2 + rp] + v2 * dg[4 + rp] + v3 * dg[6 + rp];
    float x1 = __shfl_sync(FULLM, x, (lane & ~3) + 1);
    if (rr == 0) {
        float x0 = x;
        float mx = fmaxf(x0, x1);
        float lse = mx + log1pf(expf(-fabsf(x0 - x1)));
        bool p1 = (data[bs * NN + (n + 1)] == 0.0f);   // plane1 if data==0
        g_contrib[bs * 1024 + n + 1] = (p1 ? x1 : x0) - lse;
    }
}

// ---------------- finalize: parallel reduction per sample ----------------
__global__ void amps_finalize(const float* __restrict__ data, const float* __restrict__ diag,
                              float* __restrict__ out) {
    const int bs = blockIdx.x;
    const int tid = threadIdx.x, warp = tid >> 5, lane = tid & 31;
    float4 v = ((const float4*)(g_contrib + bs * 1024))[tid];
    if (tid == 0) {
        float x0 = diag[0], x1 = diag[1];
        float mx = fmaxf(x0, x1);
        float lse = mx + log1pf(expf(-fabsf(x0 - x1)));
        v.x = ((data[bs * NN] == 0.0f) ? x1 : x0) - lse;   // n=0 contribution
    }
    float s = v.x + v.y + v.z + v.w;
#pragma unroll
    for (int o = 16; o; o >>= 1) s += __shfl_xor_sync(FULLM, s, o);
    __shared__ float ws8[8];
    if (lane == 0) ws8[warp] = s;
    __syncthreads();
    if (warp == 0) {
        float t = (lane < 8) ? ws8[lane] : 0.0f;
#pragma unroll
        for (int o = 4; o; o >>= 1) t += __shfl_xor_sync(FULLM, t, o);
        if (lane == 0) out[bs] = t;
    }
}

extern "C" void kernel_launch(void* const* d_in, const int* in_sizes, int n_in,
                              void* d_out, int out_size) {
    const float* data = (const float*)d_in[0];
    const float* tri  = (const float*)d_in[1];
    const float* diag = (const float*)d_in[2];
    float* out = (float*)d_out;

    amps_main<<<NBLK, 256>>>(data, tri);
    amps_combine<<<128, 256>>>(data, diag);
    amps_finalize<<<8, 256>>>(data, diag, out);
}